// round 12
// baseline (speedup 1.0000x reference)
#include <cuda_runtime.h>
#include <cuda_fp16.h>

// Poolpointsinterp R10: persistent kernel pipelining NCHW->NHWC(fp16) transpose
// with the per-point gather, batch by batch, via a device-side work queue.

#define SPATIAL_SCALE 0.25f
#define Nn 8
#define Cc 256
#define Hh 128
#define Ww 128

#define TILES_PER_B 1024          // 8 (C/32) x 128 (y)
#define CHUNK 16                  // points per gather item (8 warps x 2)
#define NBLOCKS 444               // 3 per SM x 148: guaranteed co-resident

// 8*128*128*256 halves = 64 MB, NHWC: [((b*H+y)*W+x)*C + c]
__device__ __half g_scr[(size_t)Nn * Hh * Ww * Cc];
__device__ int g_cnt[Nn];
__device__ int g_base[Nn + 1];
__device__ int g_cursor[Nn];
__device__ int g_perm[1 << 17];
__device__ int g_ts[Nn];          // first item index of T(b)
__device__ int g_gs[Nn];          // first item index of G(b)
__device__ int g_total_items;
__device__ int g_claim;
__device__ int g_done[Nn];

// ---------------------------------------------------------------------------
// Binning by batch (8 bins), block-aggregated.
// ---------------------------------------------------------------------------
__global__ void zero_kernel()
{
    if (threadIdx.x < Nn) { g_cnt[threadIdx.x] = 0; }
}

__global__ void bin_count(const float* __restrict__ rois, int P)
{
    __shared__ int cnt[Nn];
    int tid = threadIdx.x;
    if (tid < Nn) cnt[tid] = 0;
    __syncthreads();
    int p = blockIdx.x * blockDim.x + tid;
    if (p < P) atomicAdd(&cnt[(int)rois[p * 3]], 1);
    __syncthreads();
    if (tid < Nn && cnt[tid] > 0) atomicAdd(&g_cnt[tid], cnt[tid]);
}

__global__ void setup_kernel()
{
    if (threadIdx.x == 0) {
        int base = 0, item = 0;
        for (int b = 0; b < Nn; b++) {
            g_base[b] = base;
            g_cursor[b] = base;
            base += g_cnt[b];
            g_ts[b] = item;
            g_gs[b] = item + TILES_PER_B;
            int gc = (g_cnt[b] + CHUNK - 1) / CHUNK;
            item += TILES_PER_B + gc;
            g_done[b] = 0;
        }
        g_base[Nn] = base;
        g_total_items = item;
        g_claim = 0;
    }
}

__global__ void bin_scatter(const float* __restrict__ rois, int P)
{
    __shared__ int cnt[Nn];
    __shared__ int sbase[Nn];
    int tid = threadIdx.x;
    if (tid < Nn) cnt[tid] = 0;
    __syncthreads();
    int p = blockIdx.x * blockDim.x + tid;
    int b = -1, myidx = 0;
    if (p < P) {
        b = (int)rois[p * 3];
        myidx = atomicAdd(&cnt[b], 1);
    }
    __syncthreads();
    if (tid < Nn && cnt[tid] > 0) sbase[tid] = atomicAdd(&g_cursor[tid], cnt[tid]);
    __syncthreads();
    if (p < P) g_perm[sbase[b] + myidx] = p;
}

// ---------------------------------------------------------------------------
// ROI math + blend (full 64MB scratch addressing).
// ---------------------------------------------------------------------------
struct PointAddr {
    size_t base;
    int dx, dy;
    float w1, w2, w3, w4;
    bool valid;
};

__device__ __forceinline__ PointAddr roi_math(const float* __restrict__ rois, int p)
{
    PointAddr r;
    float rb = rois[p * 3 + 0];
    float rx = rois[p * 3 + 1];
    float ry = rois[p * 3 + 2];
    int bi = (int)rb;
    float x = rx * SPATIAL_SCALE;
    float y = ry * SPATIAL_SCALE;

    r.valid = (y >= -1.0f) & (y <= (float)Hh) & (x >= -1.0f) & (x <= (float)Ww);

    y = fmaxf(y, 0.0f);
    x = fmaxf(x, 0.0f);
    int y_low = (int)floorf(y);
    int x_low = (int)floorf(x);
    int dxs = 1, dys = 1;
    if (y_low >= Hh - 1) { y_low = Hh - 1; dys = 0; y = (float)y_low; }
    if (x_low >= Ww - 1) { x_low = Ww - 1; dxs = 0; x = (float)x_low; }

    float ly = y - (float)y_low;
    float lx = x - (float)x_low;
    float hy = 1.0f - ly;
    float hx = 1.0f - lx;
    r.w1 = hy * hx; r.w2 = hy * lx; r.w3 = ly * hx; r.w4 = ly * lx;

    r.base = ((size_t)(bi * Hh + y_low) * Ww + x_low) * 32;
    r.dx = dxs * 32;
    r.dy = dys * (Ww * 32);
    return r;
}

__device__ __forceinline__ void blend_store(
    const uint4& a, const uint4& b4, const uint4& c4, const uint4& d4,
    const PointAddr& r, float* __restrict__ out, int p, int t)
{
    const __half2* ah  = (const __half2*)&a;
    const __half2* bh2 = (const __half2*)&b4;
    const __half2* ch  = (const __half2*)&c4;
    const __half2* dh  = (const __half2*)&d4;

    float o[8];
    #pragma unroll
    for (int i = 0; i < 4; i++) {
        float2 f1 = __half22float2(ah[i]);
        float2 f2 = __half22float2(bh2[i]);
        float2 f3 = __half22float2(ch[i]);
        float2 f4 = __half22float2(dh[i]);
        o[2 * i + 0] = r.w1 * f1.x + r.w2 * f2.x + r.w3 * f3.x + r.w4 * f4.x;
        o[2 * i + 1] = r.w1 * f1.y + r.w2 * f2.y + r.w3 * f3.y + r.w4 * f4.y;
    }
    if (!r.valid) {
        #pragma unroll
        for (int i = 0; i < 8; i++) o[i] = 0.0f;
    }
    float4* dst = (float4*)(out + (size_t)p * Cc + t * 8);
    __stcs(dst + 0, make_float4(o[0], o[1], o[2], o[3]));
    __stcs(dst + 1, make_float4(o[4], o[5], o[6], o[7]));
}

// ---------------------------------------------------------------------------
// Persistent pipeline kernel.
// Work item layout per batch b: [g_ts[b] .. g_gs[b]) = transpose tiles,
//                               [g_gs[b] .. g_ts[b+1]) = gather chunks.
// ---------------------------------------------------------------------------
__global__ void __launch_bounds__(256, 4) persist_kernel(
    const float* __restrict__ feat,
    const float* __restrict__ rois,
    float* __restrict__ out)
{
    __shared__ float tile[32][129];
    __shared__ int s_item;

    int tid = threadIdx.x;
    const int total = g_total_items;

    for (;;) {
        if (tid == 0) s_item = atomicAdd(&g_claim, 1);
        __syncthreads();
        int item = s_item;
        if (item >= total) return;
        __syncthreads();   // protect s_item before next claim overwrites

        // Which batch does this item belong to?
        int b = 0;
        #pragma unroll
        for (int k = 1; k < Nn; k++) if (item >= g_ts[k]) b = k;

        if (item < g_gs[b]) {
            // ---------------- transpose tile ----------------
            int tl = item - g_ts[b];
            int cb = (tl >> 7) * 32;
            int y  = tl & 127;
            int bh = b * Hh + y;

            int c  = tid >> 3;
            int xq = tid & 7;
            const float4* src = (const float4*)(feat + (((size_t)b * Cc + cb + c) * Hh + y) * Ww);
            #pragma unroll
            for (int i = 0; i < 4; i++) {
                int f4 = i * 8 + xq;
                float4 v = __ldcs(src + f4);
                tile[c][f4 * 4 + 0] = v.x;
                tile[c][f4 * 4 + 1] = v.y;
                tile[c][f4 * 4 + 2] = v.z;
                tile[c][f4 * 4 + 3] = v.w;
            }
            __syncthreads();

            __half* dstbase = g_scr + (size_t)bh * Ww * Cc + cb;
            #pragma unroll
            for (int it = 0; it < 4; it++) {
                int idx = it * 256 + tid;
                int x = idx >> 3;
                int j = idx & 7;
                __half2 lo = __floats2half2_rn(tile[4 * j + 0][x], tile[4 * j + 1][x]);
                __half2 hi = __floats2half2_rn(tile[4 * j + 2][x], tile[4 * j + 3][x]);
                uint2 pack;
                pack.x = *(const unsigned*)&lo;
                pack.y = *(const unsigned*)&hi;
                *(uint2*)(dstbase + (size_t)x * Cc + 4 * j) = pack;
            }
            __threadfence();          // publish tile before signaling
            __syncthreads();
            if (tid == 0) atomicAdd(&g_done[b], 1);
        } else {
            // ---------------- gather chunk ----------------
            if (tid == 0) {
                while (atomicAdd(&g_done[b], 0) < TILES_PER_B) { }
                __threadfence();
            }
            __syncthreads();          // all threads see published scratch

            int gl   = item - g_gs[b];
            int pos0 = g_base[b] + gl * CHUNK + (tid >> 5) * 2;
            int end  = g_base[b + 1];
            if (pos0 < end) {
                int t = tid & 31;
                int p0 = g_perm[pos0];
                bool has1 = (pos0 + 1 < end);
                int p1 = has1 ? g_perm[pos0 + 1] : p0;

                PointAddr r0 = roi_math(rois, p0);
                PointAddr r1 = roi_math(rois, p1);

                const uint4* g = (const uint4*)g_scr;
                const uint4* q0 = g + r0.base + t;
                const uint4* q1 = g + r1.base + t;

                uint4 a0 = q0[0];
                uint4 b0 = q0[r0.dx];
                uint4 c0 = q0[r0.dy];
                uint4 d0 = q0[r0.dy + r0.dx];
                uint4 a1 = q1[0];
                uint4 b1 = q1[r1.dx];
                uint4 c1 = q1[r1.dy];
                uint4 d1 = q1[r1.dy + r1.dx];

                blend_store(a0, b0, c0, d0, r0, out, p0, t);
                if (has1)
                    blend_store(a1, b1, c1, d1, r1, out, p1, t);
            }
        }
    }
}

extern "C" void kernel_launch(void* const* d_in, const int* in_sizes, int n_in,
                              void* d_out, int out_size)
{
    const float* feat = (const float*)d_in[0];
    const float* rois = (const float*)d_in[1];
    float* out = (float*)d_out;
    int P = in_sizes[1] / 3;

    zero_kernel<<<1, 32>>>();
    bin_count<<<(P + 255) / 256, 256>>>(rois, P);
    setup_kernel<<<1, 32>>>();
    bin_scatter<<<(P + 255) / 256, 256>>>(rois, P);

    persist_kernel<<<NBLOCKS, 256>>>(feat, rois, out);
}

// round 13
// speedup vs baseline: 1.3790x; 1.3790x over previous
#include <cuda_runtime.h>
#include <cuda_fp16.h>

// Poolpointsinterp R11: software pipeline across kernel launches.
// Launch s: [blocks 0..1023] transpose batch s, [blocks 1024..2047] gather
// batch s-1. Kernel boundary = the only synchronization.

#define SPATIAL_SCALE 0.25f
#define Nn 8
#define Cc 256
#define Hh 128
#define Ww 128

#define CHUNK 16                  // points per gather chunk (8 warps x 2)
#define TBLOCKS 1024              // transpose tiles per batch: 8 (C/32) x 128 (y)
#define GBLOCKS 1024              // gather blocks per stage (grid-stride)

// 8*128*128*256 halves = 64 MB, NHWC: [((b*H+y)*W+x)*C + c]
__device__ __half g_scr[(size_t)Nn * Hh * Ww * Cc];
__device__ int g_cnt[Nn];
__device__ int g_base[Nn + 1];
__device__ int g_cursor[Nn];
__device__ int g_perm[1 << 17];

// ---------------------------------------------------------------------------
// Batch binning (8 bins, smem-aggregated -> few global atomics).
// ---------------------------------------------------------------------------
__global__ void zero_kernel()
{
    if (threadIdx.x < Nn) g_cnt[threadIdx.x] = 0;
}

__global__ void bin_count(const float* __restrict__ rois, int P)
{
    __shared__ int cnt[Nn];
    int tid = threadIdx.x;
    if (tid < Nn) cnt[tid] = 0;
    __syncthreads();
    int p = blockIdx.x * blockDim.x + tid;
    if (p < P) atomicAdd(&cnt[(int)rois[p * 3]], 1);
    __syncthreads();
    if (tid < Nn && cnt[tid] > 0) atomicAdd(&g_cnt[tid], cnt[tid]);
}

__global__ void setup_kernel()
{
    if (threadIdx.x == 0) {
        int base = 0;
        for (int b = 0; b < Nn; b++) {
            g_base[b] = base;
            g_cursor[b] = base;
            base += g_cnt[b];
        }
        g_base[Nn] = base;
    }
}

__global__ void bin_scatter(const float* __restrict__ rois, int P)
{
    __shared__ int cnt[Nn];
    __shared__ int sbase[Nn];
    int tid = threadIdx.x;
    if (tid < Nn) cnt[tid] = 0;
    __syncthreads();
    int p = blockIdx.x * blockDim.x + tid;
    int b = -1, myidx = 0;
    if (p < P) {
        b = (int)rois[p * 3];
        myidx = atomicAdd(&cnt[b], 1);
    }
    __syncthreads();
    if (tid < Nn && cnt[tid] > 0) sbase[tid] = atomicAdd(&g_cursor[tid], cnt[tid]);
    __syncthreads();
    if (p < P) g_perm[sbase[b] + myidx] = p;
}

// ---------------------------------------------------------------------------
// ROI math + blend (R7-validated).
// ---------------------------------------------------------------------------
struct PointAddr {
    size_t base;
    int dx, dy;
    float w1, w2, w3, w4;
    bool valid;
};

__device__ __forceinline__ PointAddr roi_math(const float* __restrict__ rois, int p)
{
    PointAddr r;
    float rb = rois[p * 3 + 0];
    float rx = rois[p * 3 + 1];
    float ry = rois[p * 3 + 2];
    int bi = (int)rb;
    float x = rx * SPATIAL_SCALE;
    float y = ry * SPATIAL_SCALE;

    r.valid = (y >= -1.0f) & (y <= (float)Hh) & (x >= -1.0f) & (x <= (float)Ww);

    y = fmaxf(y, 0.0f);
    x = fmaxf(x, 0.0f);
    int y_low = (int)floorf(y);
    int x_low = (int)floorf(x);
    int dxs = 1, dys = 1;
    if (y_low >= Hh - 1) { y_low = Hh - 1; dys = 0; y = (float)y_low; }
    if (x_low >= Ww - 1) { x_low = Ww - 1; dxs = 0; x = (float)x_low; }

    float ly = y - (float)y_low;
    float lx = x - (float)x_low;
    float hy = 1.0f - ly;
    float hx = 1.0f - lx;
    r.w1 = hy * hx; r.w2 = hy * lx; r.w3 = ly * hx; r.w4 = ly * lx;

    r.base = ((size_t)(bi * Hh + y_low) * Ww + x_low) * 32;
    r.dx = dxs * 32;
    r.dy = dys * (Ww * 32);
    return r;
}

__device__ __forceinline__ void blend_store(
    const uint4& a, const uint4& b4, const uint4& c4, const uint4& d4,
    const PointAddr& r, float* __restrict__ out, int p, int t)
{
    const __half2* ah  = (const __half2*)&a;
    const __half2* bh2 = (const __half2*)&b4;
    const __half2* ch  = (const __half2*)&c4;
    const __half2* dh  = (const __half2*)&d4;

    float o[8];
    #pragma unroll
    for (int i = 0; i < 4; i++) {
        float2 f1 = __half22float2(ah[i]);
        float2 f2 = __half22float2(bh2[i]);
        float2 f3 = __half22float2(ch[i]);
        float2 f4 = __half22float2(dh[i]);
        o[2 * i + 0] = r.w1 * f1.x + r.w2 * f2.x + r.w3 * f3.x + r.w4 * f4.x;
        o[2 * i + 1] = r.w1 * f1.y + r.w2 * f2.y + r.w3 * f3.y + r.w4 * f4.y;
    }
    if (!r.valid) {
        #pragma unroll
        for (int i = 0; i < 8; i++) o[i] = 0.0f;
    }
    float4* dst = (float4*)(out + (size_t)p * Cc + t * 8);
    __stcs(dst + 0, make_float4(o[0], o[1], o[2], o[3]));
    __stcs(dst + 1, make_float4(o[4], o[5], o[6], o[7]));
}

// ---------------------------------------------------------------------------
// Stage kernel: transpose batch s  ||  gather batch s-1.
// grid = TBLOCKS + GBLOCKS, block = 256.
// ---------------------------------------------------------------------------
__global__ void __launch_bounds__(256) stage_kernel(
    const float* __restrict__ feat,
    const float* __restrict__ rois,
    float* __restrict__ out,
    int s)
{
    if (blockIdx.x < TBLOCKS) {
        // -------- transpose role: batch b = s --------
        if (s >= Nn) return;
        __shared__ float tile[32][129];
        int b  = s;
        int tl = blockIdx.x;
        int cb = (tl >> 7) * 32;
        int y  = tl & 127;
        int bh = b * Hh + y;
        int tid = threadIdx.x;

        int c  = tid >> 3;
        int xq = tid & 7;
        const float4* src = (const float4*)(feat + (((size_t)b * Cc + cb + c) * Hh + y) * Ww);
        #pragma unroll
        for (int i = 0; i < 4; i++) {
            int f4 = i * 8 + xq;
            float4 v = __ldcs(src + f4);
            tile[c][f4 * 4 + 0] = v.x;
            tile[c][f4 * 4 + 1] = v.y;
            tile[c][f4 * 4 + 2] = v.z;
            tile[c][f4 * 4 + 3] = v.w;
        }
        __syncthreads();

        __half* dstbase = g_scr + (size_t)bh * Ww * Cc + cb;
        #pragma unroll
        for (int it = 0; it < 4; it++) {
            int idx = it * 256 + tid;
            int x = idx >> 3;
            int j = idx & 7;
            __half2 lo = __floats2half2_rn(tile[4 * j + 0][x], tile[4 * j + 1][x]);
            __half2 hi = __floats2half2_rn(tile[4 * j + 2][x], tile[4 * j + 3][x]);
            uint2 pack;
            pack.x = *(const unsigned*)&lo;
            pack.y = *(const unsigned*)&hi;
            *(uint2*)(dstbase + (size_t)x * Cc + 4 * j) = pack;
        }
    } else {
        // -------- gather role: batch b = s-1 --------
        if (s < 1) return;
        int b = s - 1;
        int start = g_base[b];
        int end   = g_base[b + 1];
        int k = blockIdx.x - TBLOCKS;
        int warp = threadIdx.x >> 5;
        int t = threadIdx.x & 31;
        const uint4* g = (const uint4*)g_scr;

        for (int base = start + k * CHUNK; base < end; base += GBLOCKS * CHUNK) {
            int pos0 = base + warp * 2;
            if (pos0 >= end) continue;

            int p0 = g_perm[pos0];
            bool has1 = (pos0 + 1 < end);
            int p1 = has1 ? g_perm[pos0 + 1] : p0;

            PointAddr r0 = roi_math(rois, p0);
            PointAddr r1 = roi_math(rois, p1);

            const uint4* q0 = g + r0.base + t;
            const uint4* q1 = g + r1.base + t;

            uint4 a0 = q0[0];
            uint4 b0 = q0[r0.dx];
            uint4 c0 = q0[r0.dy];
            uint4 d0 = q0[r0.dy + r0.dx];
            uint4 a1 = q1[0];
            uint4 b1 = q1[r1.dx];
            uint4 c1 = q1[r1.dy];
            uint4 d1 = q1[r1.dy + r1.dx];

            blend_store(a0, b0, c0, d0, r0, out, p0, t);
            if (has1)
                blend_store(a1, b1, c1, d1, r1, out, p1, t);
        }
    }
}

extern "C" void kernel_launch(void* const* d_in, const int* in_sizes, int n_in,
                              void* d_out, int out_size)
{
    const float* feat = (const float*)d_in[0];
    const float* rois = (const float*)d_in[1];
    float* out = (float*)d_out;
    int P = in_sizes[1] / 3;

    zero_kernel<<<1, 32>>>();
    bin_count<<<(P + 255) / 256, 256>>>(rois, P);
    setup_kernel<<<1, 32>>>();
    bin_scatter<<<(P + 255) / 256, 256>>>(rois, P);

    for (int s = 0; s <= Nn; s++) {
        stage_kernel<<<TBLOCKS + GBLOCKS, 256>>>(feat, rois, out, s);
    }
}